// round 10
// baseline (speedup 1.0000x reference)
#include <cuda_runtime.h>
#include <cuda_fp16.h>
#include <math.h>
#include <stdint.h>

#define DIMC 384
#define NH 6
#define HD 64
#define MLPD 1536
#define BATCH 8
#define SEQ 1024
#define ROWS (BATCH*SEQ)   /* 8192 */
#define BH (BATCH*NH)      /* 48 */
#define QKVW (3*DIMC)      /* 1152 */

typedef unsigned short u16;

// ---------------- scratch (fp16; activations hi/lo, weights hi only) ----------
__device__ u16 g_h_hi[ROWS*DIMC],   g_h_lo[ROWS*DIMC];      // LN out
__device__ u16 g_qkv_hi[ROWS*QKVW], g_qkv_lo[ROWS*QKVW];    // QKV out
__device__ u16 g_at_hi[ROWS*DIMC],  g_at_lo[ROWS*DIMC];     // attn out
__device__ u16 g_mlp_hi[ROWS*MLPD], g_mlp_lo[ROWS*MLPD];    // MLP hidden
__device__ u16 g_qw[QKVW*DIMC];
__device__ u16 g_pw[DIMC*DIMC];
__device__ u16 g_w1[MLPD*DIMC];
__device__ u16 g_w2[DIMC*MLPD];

__device__ __forceinline__ uint32_t smem_u32(const void* p) {
    uint32_t a;
    asm("{ .reg .u64 t; cvta.to.shared.u64 t, %1; cvt.u32.u64 %0, t; }" : "=r"(a) : "l"(p));
    return a;
}
__device__ __forceinline__ void ldm_x4(uint32_t* r, uint32_t addr) {
    asm volatile("ldmatrix.sync.aligned.m8n8.x4.shared.b16 {%0,%1,%2,%3}, [%4];"
                 : "=r"(r[0]), "=r"(r[1]), "=r"(r[2]), "=r"(r[3]) : "r"(addr));
}
__device__ __forceinline__ void ldm_x4_t(uint32_t* r, uint32_t addr) {
    asm volatile("ldmatrix.sync.aligned.m8n8.x4.trans.shared.b16 {%0,%1,%2,%3}, [%4];"
                 : "=r"(r[0]), "=r"(r[1]), "=r"(r[2]), "=r"(r[3]) : "r"(addr));
}
__device__ __forceinline__ void mma_f16(float* d, const uint32_t* a, const uint32_t* b) {
    asm volatile("mma.sync.aligned.m16n8k16.row.col.f32.f16.f16.f32 "
                 "{%0,%1,%2,%3}, {%4,%5,%6,%7}, {%8,%9}, {%0,%1,%2,%3};"
                 : "+f"(d[0]), "+f"(d[1]), "+f"(d[2]), "+f"(d[3])
                 : "r"(a[0]), "r"(a[1]), "r"(a[2]), "r"(a[3]), "r"(b[0]), "r"(b[1]));
}
__device__ __forceinline__ float f16_hi(float x) {
    return __half2float(__float2half_rn(x));
}
__device__ __forceinline__ uint32_t packh2(float x, float y) {
    __half2 t = __floats2half2_rn(x, y);
    return *(uint32_t*)&t;
}
__device__ __forceinline__ u16 h_as_u16(float x) {
    __half t = __float2half_rn(x);
    return *(u16*)&t;
}

// ---------------- all-weights convert: fp32 -> fp16, one launch ----------------
#define CVT_B0 432
#define CVT_B1 576
#define CVT_B2 1152
#define CVT_B3 1728
__global__ __launch_bounds__(256) void cvt_all(const float* __restrict__ s0,
                                               const float* __restrict__ s1,
                                               const float* __restrict__ s2,
                                               const float* __restrict__ s3,
                                               u16* d0, u16* d1, u16* d2, u16* d3)
{
    int blk = blockIdx.x;
    const float* src;
    u16* dst;
    int base;
    if (blk < CVT_B0)      { src = s0; dst = d0; base = 0; }
    else if (blk < CVT_B1) { src = s1; dst = d1; base = CVT_B0; }
    else if (blk < CVT_B2) { src = s2; dst = d2; base = CVT_B1; }
    else                   { src = s3; dst = d3; base = CVT_B2; }
    int idx = ((blk - base) * 256 + threadIdx.x) * 4;
    float4 v = *(const float4*)(src + idx);
    uint2 a;
    a.x = packh2(v.x, v.y); a.y = packh2(v.z, v.w);
    *(uint2*)(dst + idx) = a;
}

// ---------------- LayerNorm -> fp16 hi/lo (shuffle reduce) ----------------
__global__ __launch_bounds__(128) void ln_kernel(const float* __restrict__ x,
                                                 const float* __restrict__ w,
                                                 const float* __restrict__ b,
                                                 u16* __restrict__ ohi,
                                                 u16* __restrict__ olo)
{
    int row = blockIdx.x;
    const float* xr = x + (size_t)row * DIMC;
    int t = threadIdx.x;
    int lane = t & 31, wrp = t >> 5;
    float v0 = xr[t], v1 = xr[t + 128], v2 = xr[t + 256];
    __shared__ float ws[4];

    float sum = v0 + v1 + v2;
    #pragma unroll
    for (int o = 16; o > 0; o >>= 1) sum += __shfl_xor_sync(0xFFFFFFFF, sum, o);
    if (lane == 0) ws[wrp] = sum;
    __syncthreads();
    float mean = (ws[0] + ws[1] + ws[2] + ws[3]) * (1.0f / DIMC);

    float d0 = v0 - mean, d1 = v1 - mean, d2 = v2 - mean;
    float sq = d0 * d0 + d1 * d1 + d2 * d2;
    #pragma unroll
    for (int o = 16; o > 0; o >>= 1) sq += __shfl_xor_sync(0xFFFFFFFF, sq, o);
    __syncthreads();
    if (lane == 0) ws[wrp] = sq;
    __syncthreads();
    float var = (ws[0] + ws[1] + ws[2] + ws[3]) * (1.0f / DIMC);
    float r = rsqrtf(var + 1e-5f);

    size_t base = (size_t)row * DIMC;
    #pragma unroll
    for (int p = 0; p < 3; p++) {
        int i = t + p * 128;
        float d = (p == 0 ? d0 : p == 1 ? d1 : d2);
        float y = d * r * w[i] + b[i];
        float h = f16_hi(y);
        ohi[base + i] = h_as_u16(h);
        olo[base + i] = h_as_u16(y - h);
    }
}

// ================= mma.sync fp16x2 GEMM, double-buffered =================
// C[M,N] = A[M,K] @ W[N,K]^T,  acc += Ah*W + Al*W  (W single-rounded fp16).
// 256 threads (8 warps 2x4), tile TM x 128, K-chunk 32. Ping-pong smem,
// ONE __syncthreads per chunk.
// EPI 0: split-store fp16 hi/lo   EPI 1: +bias +res -> fp32   EPI 2: +bias, GELU, split-store
#define LDS_ROW 80

template<int TM, int EPI>
__global__ __launch_bounds__(256) void mma_gemm(const u16* __restrict__ Ah_,
                                                const u16* __restrict__ Al_,
                                                const u16* __restrict__ Wh_,
                                                const float* __restrict__ bias,
                                                const float* __restrict__ res,
                                                float* __restrict__ C,
                                                u16* __restrict__ Chi,
                                                u16* __restrict__ Clo,
                                                int M, int N, int K)
{
    constexpr int MI = TM / 32;
    constexpr int ABYTES = TM * LDS_ROW;
    constexpr int BUF = 2 * ABYTES + 128 * LDS_ROW;   // Ahi + Alo + W
    constexpr int NPF = (TM == 128) ? 6 : 4;
    extern __shared__ __align__(128) char smem[];
    uint32_t sbase = smem_u32(smem);

    int tid = threadIdx.x;
    int wid = tid >> 5;
    uint32_t lane = tid & 31;
    int wm = wid >> 2, wn = wid & 3;
    int n0 = blockIdx.x * 128, m0 = blockIdx.y * TM;

    float acc[MI][4][4];
    #pragma unroll
    for (int i = 0; i < MI; i++)
        #pragma unroll
        for (int j = 0; j < 4; j++)
            #pragma unroll
            for (int q = 0; q < 4; q++) acc[i][j][q] = 0.f;

    uint32_t aOff = (uint32_t)(wm * (TM / 2) + (lane & 15)) * LDS_ROW + (lane >> 4) * 16;
    uint32_t bOff = 2 * ABYTES
                    + (uint32_t)(wn * 32 + (lane & 7) + ((lane >> 4) << 3)) * LDS_ROW
                    + ((lane >> 3) & 1) * 16;

    const u16* s0 = Ah_ + (size_t)m0 * K;
    const u16* s1 = Al_ + (size_t)m0 * K;
    const u16* s2 = Wh_ + (size_t)n0 * K;

    int nchunks = K >> 5;
    uint4 pf[NPF];

    auto ld_chunk = [&](int k0) {
        #pragma unroll
        for (int p = 0; p < NPF; p++) {
            int t, i;
            if (TM == 128) { t = p >> 1; i = tid + (p & 1) * 256; }
            else           { t = (p < 2) ? p : 2; i = (p < 2) ? tid : tid + (p - 2) * 256; }
            int r = i >> 2, q = i & 3;
            const u16* src = (t == 0) ? s0 : (t == 1) ? s1 : s2;
            pf[p] = *(const uint4*)(src + (size_t)r * K + k0 + q * 8);
        }
    };
    auto st_chunk = [&](int buf) {
        #pragma unroll
        for (int p = 0; p < NPF; p++) {
            int t, i;
            if (TM == 128) { t = p >> 1; i = tid + (p & 1) * 256; }
            else           { t = (p < 2) ? p : 2; i = (p < 2) ? tid : tid + (p - 2) * 256; }
            int r = i >> 2, q = i & 3;
            int off = buf * BUF + ((t == 0) ? 0 : (t == 1) ? ABYTES : 2 * ABYTES);
            *(uint4*)(smem + off + r * LDS_ROW + q * 16) = pf[p];
        }
    };

    ld_chunk(0);
    st_chunk(0);
    __syncthreads();

    for (int c = 0; c < nchunks; c++) {
        if (c + 1 < nchunks) ld_chunk((c + 1) << 5);
        uint32_t bufb = (uint32_t)(c & 1) * BUF;

        #pragma unroll
        for (int ks = 0; ks < 2; ks++) {
            uint32_t ko = ks * 32;
            uint32_t ah[MI][4], al[MI][4], wh[2][4];
            #pragma unroll
            for (int mi = 0; mi < MI; mi++) {
                uint32_t ad = sbase + bufb + aOff + mi * (16 * LDS_ROW) + ko;
                ldm_x4(ah[mi], ad);
                ldm_x4(al[mi], ad + ABYTES);
            }
            #pragma unroll
            for (int j = 0; j < 2; j++)
                ldm_x4(wh[j], sbase + bufb + bOff + j * (16 * LDS_ROW) + ko);
            #pragma unroll
            for (int mi = 0; mi < MI; mi++) {
                #pragma unroll
                for (int nj = 0; nj < 4; nj++) {
                    const uint32_t* bp = &wh[nj >> 1][(nj & 1) * 2];
                    mma_f16(acc[mi][nj], ah[mi], bp);
                    mma_f16(acc[mi][nj], al[mi], bp);
                }
            }
        }
        if (c + 1 < nchunks) {
            st_chunk((c + 1) & 1);
            __syncthreads();
        }
    }

    // ---- epilogue ----
    #pragma unroll
    for (int mi = 0; mi < MI; mi++) {
        int r0 = m0 + wm * (TM / 2) + mi * 16 + (int)(lane >> 2);
        #pragma unroll
        for (int nj = 0; nj < 4; nj++) {
            int col = n0 + wn * 32 + nj * 8 + (int)(lane & 3) * 2;
            float v[4];
            #pragma unroll
            for (int q = 0; q < 4; q++) v[q] = acc[mi][nj][q];
            if (EPI == 1 || EPI == 2) {
                float2 bb = *(const float2*)(bias + col);
                v[0] += bb.x; v[1] += bb.y; v[2] += bb.x; v[3] += bb.y;
            }
            if (EPI == 1) {
                float2 ra = *(const float2*)(res + (size_t)r0 * N + col);
                float2 rb = *(const float2*)(res + (size_t)(r0 + 8) * N + col);
                v[0] += ra.x; v[1] += ra.y; v[2] += rb.x; v[3] += rb.y;
            }
            if (EPI == 2) {
                #pragma unroll
                for (int q = 0; q < 4; q++)
                    v[q] = 0.5f * v[q] * (1.0f + erff(v[q] * 0.7071067811865476f));
            }
            if (EPI == 1) {
                float2 o0; o0.x = v[0]; o0.y = v[1];
                float2 o1; o1.x = v[2]; o1.y = v[3];
                *(float2*)(C + (size_t)r0 * N + col) = o0;
                *(float2*)(C + (size_t)(r0 + 8) * N + col) = o1;
            } else {
                float h0 = f16_hi(v[0]), h1 = f16_hi(v[1]);
                float h2 = f16_hi(v[2]), h3 = f16_hi(v[3]);
                *(uint32_t*)(Chi + (size_t)r0 * N + col)       = packh2(h0, h1);
                *(uint32_t*)(Chi + (size_t)(r0 + 8) * N + col) = packh2(h2, h3);
                *(uint32_t*)(Clo + (size_t)r0 * N + col)       = packh2(v[0] - h0, v[1] - h1);
                *(uint32_t*)(Clo + (size_t)(r0 + 8) * N + col) = packh2(v[2] - h2, v[3] - h3);
            }
        }
    }
}

// ================= tensor-core L2Q attention (fp16, double-buffered K/V) ======
// 128 queries x one (b,h) per block, 8 warps x 16 query rows.
// S = (Qh+Ql)@K^T, f = relu(a's^2+b's+g); P rounded to fp16, rowsum over
// ROUNDED P. K,V single fp16, ping-pong buffers, one sync per chunk.
#define AROW 144
#define A_QH 0
#define A_QL 18432
#define A_KV0 36864          /* K 9216 + V 9216 per buffer */
#define KVBUF 18432
#define ATTN_SMEM (36864 + 2 * KVBUF)   /* 73728 */

__global__ __launch_bounds__(256) void attn_mma(const u16* __restrict__ qh,
                                                const u16* __restrict__ ql,
                                                const float* __restrict__ alpha,
                                                const float* __restrict__ beta,
                                                const float* __restrict__ gamma,
                                                u16* __restrict__ ohi,
                                                u16* __restrict__ olo)
{
    extern __shared__ char sm[];
    uint32_t sb = smem_u32(sm);
    int tid = threadIdx.x;
    int wid = tid >> 5;
    uint32_t lane = tid & 31;
    int bh = blockIdx.y;
    int b = bh / NH, h = bh % NH;
    int q0 = blockIdx.x * 128;
    float al2 = alpha[h] * 0.015625f;
    float be2 = beta[h] * 0.125f;
    float ga = gamma[h];

    size_t rowbase = (size_t)b * SEQ * QKVW;

    // K/V chunk prefetch regs
    uint4 pf[4];
    auto ld_kv = [&](int c) {
        #pragma unroll
        for (int p = 0; p < 4; p++) {
            int t = p >> 1;
            int coloff = (t == 0) ? (DIMC + h * HD) : (2 * DIMC + h * HD);
            int i = tid + (p & 1) * 256;
            int r = i >> 3, q = i & 7;
            pf[p] = *(const uint4*)(qh + rowbase + (size_t)(c * 64 + r) * QKVW + coloff + q * 8);
        }
    };
    auto st_kv = [&](int buf) {
        #pragma unroll
        for (int p = 0; p < 4; p++) {
            int t = p >> 1;
            int soff = A_KV0 + buf * KVBUF + ((t == 0) ? 0 : 9216);
            int i = tid + (p & 1) * 256;
            int r = i >> 3, q = i & 7;
            *(uint4*)(sm + soff + r * AROW + q * 16) = pf[p];
        }
    };

    // ---- stage Q tile (128 x 64, hi+lo) + first K/V chunk ----
    ld_kv(0);
    #pragma unroll
    for (int p = 0; p < 8; p++) {
        const u16* src = (p < 4) ? qh : ql;
        int soff = (p < 4) ? A_QH : A_QL;
        int i = tid + (p & 3) * 256;
        int r = i >> 3, q = i & 7;
        uint4 v = *(const uint4*)(src + rowbase + (size_t)(q0 + r) * QKVW + h * HD + q * 8);
        *(uint4*)(sm + soff + r * AROW + q * 16) = v;
    }
    st_kv(0);
    __syncthreads();

    uint32_t aOffQ = (uint32_t)(wid * 16 + (lane & 15)) * AROW + (lane >> 4) * 16;
    uint32_t ah[4][4], al[4][4];
    #pragma unroll
    for (int ks = 0; ks < 4; ks++) {
        ldm_x4(ah[ks], sb + A_QH + aOffQ + ks * 32);
        ldm_x4(al[ks], sb + A_QL + aOffQ + ks * 32);
    }

    float o[8][4];
    #pragma unroll
    for (int d = 0; d < 8; d++)
        #pragma unroll
        for (int q = 0; q < 4; q++) o[d][q] = 0.f;
    float rs0 = 0.f, rs1 = 0.f;

    uint32_t kb = (uint32_t)((lane & 7) + ((lane >> 4) << 3)) * AROW + ((lane >> 3) & 1) * 16;
    uint32_t vb = (uint32_t)((lane & 7) + (((lane >> 3) & 1) << 3)) * AROW + (lane >> 4) * 16;

    for (int c = 0; c < SEQ / 64; c++) {
        if (c + 1 < SEQ / 64) ld_kv(c + 1);
        uint32_t kbase = sb + A_KV0 + (uint32_t)(c & 1) * KVBUF;
        uint32_t vbase = kbase + 9216;

        // ---- S = Q @ K^T ----
        float s[8][4];
        #pragma unroll
        for (int nf = 0; nf < 8; nf++)
            #pragma unroll
            for (int q = 0; q < 4; q++) s[nf][q] = 0.f;
        #pragma unroll
        for (int ks = 0; ks < 4; ks++) {
            uint32_t khf[4][4];
            #pragma unroll
            for (int g = 0; g < 4; g++)
                ldm_x4(khf[g], kbase + kb + g * (16 * AROW) + ks * 32);
            #pragma unroll
            for (int nf = 0; nf < 8; nf++) {
                const uint32_t* bp = &khf[nf >> 1][(nf & 1) * 2];
                mma_f16(s[nf], ah[ks], bp);
                mma_f16(s[nf], al[ks], bp);
            }
        }
        // ---- activation ----
        #pragma unroll
        for (int nf = 0; nf < 8; nf++) {
            #pragma unroll
            for (int q = 0; q < 4; q++) {
                float xv = s[nf][q];
                float f = fmaf(al2 * xv, xv, fmaf(be2, xv, ga));
                s[nf][q] = fmaxf(f, 0.f);
            }
        }
        // ---- O += round(P) @ V ; rowsum over ROUNDED P ----
        #pragma unroll
        for (int ks = 0; ks < 4; ks++) {
            float h00 = f16_hi(s[2*ks][0]), h01 = f16_hi(s[2*ks][1]);
            float h02 = f16_hi(s[2*ks][2]), h03 = f16_hi(s[2*ks][3]);
            float h10 = f16_hi(s[2*ks+1][0]), h11 = f16_hi(s[2*ks+1][1]);
            float h12 = f16_hi(s[2*ks+1][2]), h13 = f16_hi(s[2*ks+1][3]);
            rs0 += h00 + h01 + h10 + h11;
            rs1 += h02 + h03 + h12 + h13;
            uint32_t ph[4];
            ph[0] = packh2(h00, h01); ph[1] = packh2(h02, h03);
            ph[2] = packh2(h10, h11); ph[3] = packh2(h12, h13);

            uint32_t vhf[4][4];
            #pragma unroll
            for (int g = 0; g < 4; g++)
                ldm_x4_t(vhf[g], vbase + vb + ks * (16 * AROW) + g * 32);
            #pragma unroll
            for (int df = 0; df < 8; df++)
                mma_f16(o[df], ph, &vhf[df >> 1][(df & 1) * 2]);
        }

        if (c + 1 < SEQ / 64) {
            st_kv((c + 1) & 1);
            __syncthreads();
        }
    }

    rs0 += __shfl_xor_sync(0xFFFFFFFF, rs0, 1);
    rs0 += __shfl_xor_sync(0xFFFFFFFF, rs0, 2);
    rs1 += __shfl_xor_sync(0xFFFFFFFF, rs1, 1);
    rs1 += __shfl_xor_sync(0xFFFFFFFF, rs1, 2);
    float inv0 = 1.0f / (rs0 + 1e-6f);
    float inv1 = 1.0f / (rs1 + 1e-6f);

    int grow = b * SEQ + q0 + wid * 16 + (int)(lane >> 2);
    #pragma unroll
    for (int df = 0; df < 8; df++) {
        int col = h * HD + df * 8 + (int)(lane & 3) * 2;
        float v0 = o[df][0] * inv0, v1 = o[df][1] * inv0;
        float v2 = o[df][2] * inv1, v3 = o[df][3] * inv1;
        float h0 = f16_hi(v0), h1 = f16_hi(v1), h2 = f16_hi(v2), h3 = f16_hi(v3);
        *(uint32_t*)(ohi + (size_t)grow * DIMC + col)       = packh2(h0, h1);
        *(uint32_t*)(ohi + (size_t)(grow + 8) * DIMC + col) = packh2(h2, h3);
        *(uint32_t*)(olo + (size_t)grow * DIMC + col)       = packh2(v0 - h0, v1 - h1);
        *(uint32_t*)(olo + (size_t)(grow + 8) * DIMC + col) = packh2(v2 - h2, v3 - h3);
    }
}

// ---------------- launch ------------------------------------------------------
extern "C" void kernel_launch(void* const* d_in, const int* in_sizes, int n_in,
                              void* d_out, int out_size)
{
    const float* x      = (const float*)d_in[0];
    const float* qkv_w  = (const float*)d_in[1];
    const float* proj_w = (const float*)d_in[2];
    const float* proj_b = (const float*)d_in[3];
    const float* alpha  = (const float*)d_in[4];
    const float* beta   = (const float*)d_in[5];
    const float* gamma  = (const float*)d_in[6];
    const float* ln1_w  = (const float*)d_in[7];
    const float* ln1_b  = (const float*)d_in[8];
    const float* ln2_w  = (const float*)d_in[9];
    const float* ln2_b  = (const float*)d_in[10];
    const float* w1     = (const float*)d_in[11];
    const float* b1     = (const float*)d_in[12];
    const float* w2     = (const float*)d_in[13];
    const float* b2     = (const float*)d_in[14];
    float* out = (float*)d_out;

    u16 *hh, *hl, *qvh, *qvl, *ath, *atl, *mph, *mpl;
    u16 *qw, *pw, *w1h, *w2h;
    cudaGetSymbolAddress((void**)&hh,  g_h_hi);   cudaGetSymbolAddress((void**)&hl,  g_h_lo);
    cudaGetSymbolAddress((void**)&qvh, g_qkv_hi); cudaGetSymbolAddress((void**)&qvl, g_qkv_lo);
    cudaGetSymbolAddress((void**)&ath, g_at_hi);  cudaGetSymbolAddress((void**)&atl, g_at_lo);
    cudaGetSymbolAddress((void**)&mph, g_mlp_hi); cudaGetSymbolAddress((void**)&mpl, g_mlp_lo);
    cudaGetSymbolAddress((void**)&qw,  g_qw);
    cudaGetSymbolAddress((void**)&pw,  g_pw);
    cudaGetSymbolAddress((void**)&w1h, g_w1);
    cudaGetSymbolAddress((void**)&w2h, g_w2);

    const int GS128 = 2 * (2 * 128 * LDS_ROW + 128 * LDS_ROW);  // 61440
    const int GS64  = 2 * (2 * 64 * LDS_ROW + 128 * LDS_ROW);   // 40960
    cudaFuncSetAttribute(attn_mma, cudaFuncAttributeMaxDynamicSharedMemorySize, ATTN_SMEM);
    cudaFuncSetAttribute(mma_gemm<128, 0>, cudaFuncAttributeMaxDynamicSharedMemorySize, GS128);
    cudaFuncSetAttribute(mma_gemm<128, 2>, cudaFuncAttributeMaxDynamicSharedMemorySize, GS128);
    cudaFuncSetAttribute(mma_gemm<64, 1>, cudaFuncAttributeMaxDynamicSharedMemorySize, GS64);

    // 0) convert all weights to fp16 (one launch)
    cvt_all<<<CVT_B3, 256>>>(qkv_w, proj_w, w1, w2, qw, pw, w1h, w2h);
    // 1) LN1 -> fp16 hi/lo
    ln_kernel<<<ROWS, 128>>>(x, ln1_w, ln1_b, hh, hl);
    // 2) QKV gemm -> fp16 hi/lo
    mma_gemm<128, 0><<<dim3(QKVW / 128, ROWS / 128), 256, GS128>>>(
        hh, hl, qw, nullptr, nullptr, nullptr, qvh, qvl, ROWS, QKVW, DIMC);
    // 3) attention -> fp16 hi/lo
    attn_mma<<<dim3(SEQ / 128, BH), 256, ATTN_SMEM>>>(qvh, qvl, alpha, beta, gamma, ath, atl);
    // 4) proj + bias + residual(x) -> out fp32
    mma_gemm<64, 1><<<dim3(DIMC / 128, ROWS / 64), 256, GS64>>>(
        ath, atl, pw, proj_b, x, out, nullptr, nullptr, ROWS, DIMC, DIMC);
    // 5) LN2 -> fp16 hi/lo
    ln_kernel<<<ROWS, 128>>>(out, ln2_w, ln2_b, hh, hl);
    // 6) MLP1 + bias + GELU -> fp16 hi/lo
    mma_gemm<128, 2><<<dim3(MLPD / 128, ROWS / 128), 256, GS128>>>(
        hh, hl, w1h, b1, nullptr, nullptr, mph, mpl, ROWS, MLPD, DIMC);
    // 7) MLP2 + bias + residual(out) -> out fp32
    mma_gemm<64, 1><<<dim3(DIMC / 128, ROWS / 64), 256, GS64>>>(
        mph, mpl, w2h, b2, out, out, nullptr, nullptr, ROWS, DIMC, MLPD);
}